// round 11
// baseline (speedup 1.0000x reference)
// v5 — 3 barriers/step, rh/z in smem, launch-parity for ncu capture of recurrence
#include <cuda_runtime.h>
#include <cstdint>

#define SEQ 512
#define BATCH 64
#define IDIM 1024
#define HDIM 1024
#define G3 3072
#define CHUNK 64
#define NCHUNK (SEQ / CHUNK)
#define NCTA 128

// ---------------- scratch ----------------
__device__ float g_gx[(size_t)CHUNK * BATCH * G3];   // 50 MB
__device__ float g_h[BATCH * HDIM];
__device__ float g_partA[4 * 32 * 64 * 64];          // [ksA*32+ngA][b][nc]  (r|z partials)
__device__ float g_partB[8 * 16 * 64 * 64];          // [ksB*16+ngB][b][nc]  (n partials)
__device__ unsigned g_flags[NCTA];                   // monotonic barrier flags

typedef unsigned long long ull;

// ---------------- f32x2 helpers (kept for gemm; proven neutral but working) ----
__device__ __forceinline__ ull pack2(float x, float y) {
    ull r; asm("mov.b64 %0, {%1, %2};" : "=l"(r) : "f"(x), "f"(y)); return r;
}
__device__ __forceinline__ void unpack2(ull v, float& x, float& y) {
    asm("mov.b64 {%0, %1}, %2;" : "=f"(x), "=f"(y) : "l"(v));
}
__device__ __forceinline__ void fma2(ull& d, ull a, ull b) {
    asm("fma.rn.f32x2 %0, %1, %2, %0;" : "+l"(d) : "l"(a), "l"(b));
}

// ---------------- spin-safe flag access ----------------
__device__ __forceinline__ uint4 ld_flags4(const unsigned* p) {
    uint4 v;
    asm volatile("ld.global.cg.v4.u32 {%0,%1,%2,%3}, [%4];"
                 : "=r"(v.x), "=r"(v.y), "=r"(v.z), "=r"(v.w)
                 : "l"(p) : "memory");
    return v;
}
__device__ __forceinline__ void st_flag(unsigned* p, unsigned v) {
    asm volatile("st.global.cg.u32 [%0], %1;" :: "l"(p), "r"(v) : "memory");
}

// ---------------- flag-array grid barrier ----------------
__device__ __forceinline__ void bar_sync(int bid, unsigned target)
{
    __syncthreads();
    if (threadIdx.x < 32) {
        if (threadIdx.x == 0) {
            asm volatile("membar.gl;" ::: "memory");   // release (cumulative via bar.sync)
            st_flag(&g_flags[bid], target);
        }
        bool ok; int spins = 0;
        do {
            uint4 v = ld_flags4(&g_flags[threadIdx.x * 4]);
            ok = v.x >= target && v.y >= target && v.z >= target && v.w >= target;
            if (!ok && ++spins > 128) __nanosleep(64);
        } while (!__all_sync(0xffffffffu, ok));
        asm volatile("membar.gl;" ::: "memory");       // acquire
    }
    __syncthreads();
}

// ---------------- flag zero (also shifts ncu capture slot to a recurrence) ----
__global__ void flag_zero_kernel()
{
    if (threadIdx.x < NCTA) g_flags[threadIdx.x] = 0;
}

// ---------------- gx GEMM: C[4096,3072] = A @ W_ih^T + b (unchanged) ----------
__global__ void __launch_bounds__(256) gemm_gx_kernel(
    const float* __restrict__ A, const float* __restrict__ W,
    const float* __restrict__ bias)
{
    __shared__ float As[16][132];
    __shared__ float Bs[16][68];

    const int bm = blockIdx.y * 128;
    const int bn = blockIdx.x * 64;
    const int tid = threadIdx.x;

    ull acc[8][2];
#pragma unroll
    for (int i = 0; i < 8; i++) { acc[i][0] = 0ull; acc[i][1] = 0ull; }

    const int tx = tid & 15;
    const int ty = tid >> 4;

    for (int k0 = 0; k0 < IDIM; k0 += 16) {
#pragma unroll
        for (int j = 0; j < 2; j++) {
            int lid = tid + j * 256;
            int row = lid >> 2;
            int kk  = (lid & 3) * 4;
            float4 v = *(const float4*)&A[(size_t)(bm + row) * IDIM + k0 + kk];
            As[kk + 0][row] = v.x; As[kk + 1][row] = v.y;
            As[kk + 2][row] = v.z; As[kk + 3][row] = v.w;
        }
        {
            int row = tid >> 2;
            int kk  = (tid & 3) * 4;
            float4 v = *(const float4*)&W[(size_t)(bn + row) * IDIM + k0 + kk];
            Bs[kk + 0][row] = v.x; Bs[kk + 1][row] = v.y;
            Bs[kk + 2][row] = v.z; Bs[kk + 3][row] = v.w;
        }
        __syncthreads();

#pragma unroll
        for (int kk = 0; kk < 16; kk++) {
            float4 a0 = *(const float4*)&As[kk][ty * 8];
            float4 a1 = *(const float4*)&As[kk][ty * 8 + 4];
            ulonglong2 b2 = *(const ulonglong2*)&Bs[kk][tx * 4];
            float av[8] = {a0.x, a0.y, a0.z, a0.w, a1.x, a1.y, a1.z, a1.w};
#pragma unroll
            for (int i = 0; i < 8; i++) {
                ull ad = pack2(av[i], av[i]);
                fma2(acc[i][0], ad, b2.x);
                fma2(acc[i][1], ad, b2.y);
            }
        }
        __syncthreads();
    }

#pragma unroll
    for (int i = 0; i < 8; i++) {
        int m = bm + ty * 8 + i;
        float c0, c1, c2, c3;
        unpack2(acc[i][0], c0, c1);
        unpack2(acc[i][1], c2, c3);
        int n = bn + tx * 4;
        g_gx[(size_t)m * G3 + n + 0] = c0 + bias[n + 0];
        g_gx[(size_t)m * G3 + n + 1] = c1 + bias[n + 1];
        g_gx[(size_t)m * G3 + n + 2] = c2 + bias[n + 2];
        g_gx[(size_t)m * G3 + n + 3] = c3 + bias[n + 3];
    }
}

// ---------------- init h ----------------
__global__ void init_h_kernel(const float* __restrict__ h0)
{
    int i = blockIdx.x * blockDim.x + threadIdx.x;
    if (i < BATCH * HDIM) g_h[i] = h0[i];
}

// ---------------- persistent recurrence (3 barriers/step) ----------------
// smem (floats): WsA[256][68], WsB[128][68], HsA[256][68]; HsB overlays the
// half of HsA not used as the rh source (phase-B k-range ⊆ phase-A k-range).
#define SM_WA 0
#define SM_WB (256 * 68)
#define SM_HA (SM_WB + 128 * 68)
#define SMEM_FLOATS (SM_HA + 256 * 68)   // 43520 floats = 174,080 B

__global__ void __launch_bounds__(256, 1) recurrence_kernel(
    int c0, const float* __restrict__ Whh, const float* __restrict__ bhh,
    float* __restrict__ Y)
{
    extern __shared__ float sm[];
    float* WsA = sm + SM_WA;
    float* WsB = sm + SM_WB;
    float* HsA = sm + SM_HA;

    const int tid = threadIdx.x;
    const int bid = blockIdx.x;
    const int gtid = bid * 256 + tid;

    // phase A role: 32 n-groups x 4 k-splits
    const int ksA = bid & 3, ngA = bid >> 2;
    const int kA0 = ksA * 256, nA0 = ngA * 64;
    // phase B role: chosen so [kB0,kB0+128) ⊆ [kA0,kA0+256)
    const int e   = (bid >> 2) & 1;
    const int ksB = (bid & 3) * 2 + e;       // bijection over 0..7
    const int ngB = bid >> 3;
    const int kB0 = ksB * 128;               // == kA0 + 128*e
    const int nB0 = ngB * 64;

    float* HsB = HsA + (e ? 0 : 128 * 68);   // disjoint from rh source rows

    // resident weights (k-major, stride 68)
    for (int idx = tid; idx < 64 * 256; idx += 256) {
        int n = idx >> 8, k = idx & 255;
        WsA[k * 68 + n] = __ldg(&Whh[(size_t)(nA0 + n) * HDIM + kA0 + k]);
    }
    for (int idx = tid; idx < 64 * 128; idx += 256) {
        int n = idx >> 7, k = idx & 127;
        WsB[k * 68 + n] = __ldg(&Whh[(size_t)(2048 + nB0 + n) * HDIM + kB0 + k]);
    }

    const int tx = tid & 15, ty = tid >> 4;
    const int b0 = ty * 4;                   // batch base for GEMM tiles
    const int cA = tx * 4;                   // n-col base

    // rh-build mapping
    const int ncR = tid & 63;                // n within 64-group (warp-coalesced)
    const int bbR = tid >> 6;                // 0..3

    unsigned target;
    {
        unsigned t0;
        asm volatile("ld.global.cg.u32 %0, [%1];" : "=r"(t0)
                     : "l"(&g_flags[bid]) : "memory");
        target = t0;
    }

    __syncthreads();

    for (int tc = 0; tc < CHUNK; tc++) {
        const float* gx_t = g_gx + (size_t)tc * BATCH * G3;

        // ---- stage h slice [256 k x 64 b], k-major ----
        for (int it = tid; it < 64 * 64; it += 256) {
            int q = it >> 6;          // k-quad 0..63
            int b = it & 63;
            float4 v = __ldcg((const float4*)&g_h[b * HDIM + kA0 + q * 4]);
            HsA[(q * 4 + 0) * 68 + b] = v.x;
            HsA[(q * 4 + 1) * 68 + b] = v.y;
            HsA[(q * 4 + 2) * 68 + b] = v.z;
            HsA[(q * 4 + 3) * 68 + b] = v.w;
        }
        __syncthreads();

        // ---- phase A GEMM: partial[64b x 64n] over k in [kA0,kA0+256) ----
        {
            float acc[4][4];
#pragma unroll
            for (int i = 0; i < 4; i++)
#pragma unroll
                for (int j = 0; j < 4; j++) acc[i][j] = 0.f;

#pragma unroll 8
            for (int kk = 0; kk < 256; kk++) {
                float4 h4 = *(const float4*)&HsA[kk * 68 + b0];
                float4 w4 = *(const float4*)&WsA[kk * 68 + cA];
                acc[0][0] += h4.x * w4.x; acc[0][1] += h4.x * w4.y;
                acc[0][2] += h4.x * w4.z; acc[0][3] += h4.x * w4.w;
                acc[1][0] += h4.y * w4.x; acc[1][1] += h4.y * w4.y;
                acc[1][2] += h4.y * w4.z; acc[1][3] += h4.y * w4.w;
                acc[2][0] += h4.z * w4.x; acc[2][1] += h4.z * w4.y;
                acc[2][2] += h4.z * w4.z; acc[2][3] += h4.z * w4.w;
                acc[3][0] += h4.w * w4.x; acc[3][1] += h4.w * w4.y;
                acc[3][2] += h4.w * w4.z; acc[3][3] += h4.w * w4.w;
            }

            float* pA = g_partA + ((size_t)(ksA * 32 + ngA)) * 4096;
#pragma unroll
            for (int i = 0; i < 4; i++)
                *(float4*)&pA[(b0 + i) * 64 + cA] =
                    make_float4(acc[i][0], acc[i][1], acc[i][2], acc[i][3]);
        }
        bar_sync(bid, ++target);   // barrier 1: partA visible

        // ---- build rh slice [128 k x 64 b] in smem (replaces finalize A) ----
        {
#pragma unroll
            for (int g = 0; g < 2; g++) {
                int n = kB0 + g * 64 + ncR;       // r-gate col == k index (<1024)
                int ngGrp = n >> 6;
                float bv = __ldg(&bhh[n]);
                int rsrc = (n - kA0) * 68;        // rh source row in HsA
                int rdst = (n - kB0) * 68;        // dest row in HsB
#pragma unroll 4
                for (int j = 0; j < 16; j++) {
                    int b = bbR * 16 + j;
                    const float* pA = g_partA + (size_t)ngGrp * 4096 + b * 64 + ncR;
                    float ps = __ldcg(pA + (size_t)0 * 32 * 4096)
                             + __ldcg(pA + (size_t)1 * 32 * 4096)
                             + __ldcg(pA + (size_t)2 * 32 * 4096)
                             + __ldcg(pA + (size_t)3 * 32 * 4096);
                    float x = ps + __ldg(&gx_t[(size_t)b * G3 + n]) + bv;
                    float r = 1.f / (1.f + __expf(-x));
                    HsB[rdst + b] = r * HsA[rsrc + b];
                }
            }
        }
        __syncthreads();

        // ---- phase B GEMM: partial[64b x 64n] over k in [kB0,kB0+128) ----
        {
            float acc[4][4];
#pragma unroll
            for (int i = 0; i < 4; i++)
#pragma unroll
                for (int j = 0; j < 4; j++) acc[i][j] = 0.f;

#pragma unroll 8
            for (int kk = 0; kk < 128; kk++) {
                float4 h4 = *(const float4*)&HsB[kk * 68 + b0];
                float4 w4 = *(const float4*)&WsB[kk * 68 + cA];
                acc[0][0] += h4.x * w4.x; acc[0][1] += h4.x * w4.y;
                acc[0][2] += h4.x * w4.z; acc[0][3] += h4.x * w4.w;
                acc[1][0] += h4.y * w4.x; acc[1][1] += h4.y * w4.y;
                acc[1][2] += h4.y * w4.z; acc[1][3] += h4.y * w4.w;
                acc[2][0] += h4.z * w4.x; acc[2][1] += h4.z * w4.y;
                acc[2][2] += h4.z * w4.z; acc[2][3] += h4.z * w4.w;
                acc[3][0] += h4.w * w4.x; acc[3][1] += h4.w * w4.y;
                acc[3][2] += h4.w * w4.z; acc[3][3] += h4.w * w4.w;
            }

            float* pB = g_partB + ((size_t)(ksB * 16 + ngB)) * 4096;
#pragma unroll
            for (int i = 0; i < 4; i++)
                *(float4*)&pB[(b0 + i) * 64 + cA] =
                    make_float4(acc[i][0], acc[i][1], acc[i][2], acc[i][3]);
        }
        bar_sync(bid, ++target);   // barrier 2: partB visible

        // ---- finalize: z from partA, n from partB, blend, write h & Y ----
        {
            int e0 = gtid * 2;
            int b = e0 >> 10, n = e0 & 1023;
            int ng2 = n >> 6, nc2 = n & 63;

            const float* baseN = g_partB + (size_t)ng2 * 4096 + b * 64 + nc2;
            float nx = 0.f, ny = 0.f;
#pragma unroll
            for (int ks = 0; ks < 8; ks++) {
                float2 p = __ldcg((const float2*)(baseN + (size_t)ks * 16 * 4096));
                nx += p.x; ny += p.y;
            }
            const float* baseZ = g_partA + (size_t)(16 + ng2) * 4096 + b * 64 + nc2;
            float zx = 0.f, zy = 0.f;
#pragma unroll
            for (int ks = 0; ks < 4; ks++) {
                float2 p = __ldcg((const float2*)(baseZ + (size_t)ks * 32 * 4096));
                zx += p.x; zy += p.y;
            }

            float2 gZ = __ldg((const float2*)&gx_t[(size_t)b * G3 + 1024 + n]);
            float2 gN = __ldg((const float2*)&gx_t[(size_t)b * G3 + 2048 + n]);
            float2 bZ = __ldg((const float2*)&bhh[1024 + n]);
            float2 bN = __ldg((const float2*)&bhh[2048 + n]);

            float z0 = 1.f / (1.f + __expf(-(zx + gZ.x + bZ.x)));
            float z1 = 1.f / (1.f + __expf(-(zy + gZ.y + bZ.y)));
            float n0 = 2.f / (1.f + __expf(-2.f * (nx + gN.x + bN.x))) - 1.f;
            float n1 = 2.f / (1.f + __expf(-2.f * (ny + gN.y + bN.y))) - 1.f;

            float2 ho = __ldcg((const float2*)&g_h[b * HDIM + n]);
            float hn0 = (1.f - z0) * n0 + z0 * ho.x;
            float hn1 = (1.f - z1) * n1 + z1 * ho.y;
            *(float2*)&g_h[b * HDIM + n] = make_float2(hn0, hn1);
            int t = c0 + tc;
            *(float2*)&Y[((size_t)t * BATCH + b) * HDIM + n] = make_float2(hn0, hn1);
        }
        if (tc < CHUNK - 1) bar_sync(bid, ++target);   // barrier 3
    }
}

// ---------------- write Y_h ----------------
__global__ void write_yh_kernel(float* __restrict__ out_tail)
{
    int i = blockIdx.x * blockDim.x + threadIdx.x;
    if (i < BATCH * HDIM) out_tail[i] = g_h[i];
}

// ---------------- launch ----------------
extern "C" void kernel_launch(void* const* d_in, const int* in_sizes, int n_in,
                              void* d_out, int out_size)
{
    const float* input  = (const float*)d_in[0];
    const float* h0     = (const float*)d_in[1];
    const float* w_ih   = (const float*)d_in[2];
    const float* w_hh   = (const float*)d_in[3];
    const float* b_ih   = (const float*)d_in[4];
    const float* b_hh   = (const float*)d_in[5];
    float* out = (float*)d_out;

    const int smem_bytes = SMEM_FLOATS * sizeof(float);   // 174,080 B
    cudaFuncSetAttribute(recurrence_kernel,
                         cudaFuncAttributeMaxDynamicSharedMemorySize, smem_bytes);

    init_h_kernel<<<(BATCH * HDIM + 255) / 256, 256>>>(h0);   // launch 1
    flag_zero_kernel<<<1, 128>>>();                            // launch 2 (parity)

    dim3 ggrid(G3 / 64, (CHUNK * BATCH) / 128);
    for (int c = 0; c < NCHUNK; c++) {
        gemm_gx_kernel<<<ggrid, 256>>>(input + (size_t)c * CHUNK * BATCH * IDIM, w_ih, b_ih);
        recurrence_kernel<<<NCTA, 256, smem_bytes>>>(c * CHUNK, w_hh, b_hh, out);
    }

    write_yh_kernel<<<(BATCH * HDIM + 255) / 256, 256>>>(out + (size_t)SEQ * BATCH * HDIM);
}

// round 12
// speedup vs baseline: 1.0037x; 1.0037x over previous
// v5 — 3 barriers/step, rh/z in smem, launch-parity for ncu capture of recurrence
#include <cuda_runtime.h>
#include <cstdint>

#define SEQ 512
#define BATCH 64
#define IDIM 1024
#define HDIM 1024
#define G3 3072
#define CHUNK 64
#define NCHUNK (SEQ / CHUNK)
#define NCTA 128

// ---------------- scratch ----------------
__device__ float g_gx[(size_t)CHUNK * BATCH * G3];   // 50 MB
__device__ float g_h[BATCH * HDIM];
__device__ float g_partA[4 * 32 * 64 * 64];          // [ksA*32+ngA][b][nc]  (r|z partials)
__device__ float g_partB[8 * 16 * 64 * 64];          // [ksB*16+ngB][b][nc]  (n partials)
__device__ unsigned g_flags[NCTA];                   // monotonic barrier flags

typedef unsigned long long ull;

// ---------------- f32x2 helpers (kept for gemm; proven neutral but working) ----
__device__ __forceinline__ ull pack2(float x, float y) {
    ull r; asm("mov.b64 %0, {%1, %2};" : "=l"(r) : "f"(x), "f"(y)); return r;
}
__device__ __forceinline__ void unpack2(ull v, float& x, float& y) {
    asm("mov.b64 {%0, %1}, %2;" : "=f"(x), "=f"(y) : "l"(v));
}
__device__ __forceinline__ void fma2(ull& d, ull a, ull b) {
    asm("fma.rn.f32x2 %0, %1, %2, %0;" : "+l"(d) : "l"(a), "l"(b));
}

// ---------------- spin-safe flag access ----------------
__device__ __forceinline__ uint4 ld_flags4(const unsigned* p) {
    uint4 v;
    asm volatile("ld.global.cg.v4.u32 {%0,%1,%2,%3}, [%4];"
                 : "=r"(v.x), "=r"(v.y), "=r"(v.z), "=r"(v.w)
                 : "l"(p) : "memory");
    return v;
}
__device__ __forceinline__ void st_flag(unsigned* p, unsigned v) {
    asm volatile("st.global.cg.u32 [%0], %1;" :: "l"(p), "r"(v) : "memory");
}

// ---------------- flag-array grid barrier ----------------
__device__ __forceinline__ void bar_sync(int bid, unsigned target)
{
    __syncthreads();
    if (threadIdx.x < 32) {
        if (threadIdx.x == 0) {
            asm volatile("membar.gl;" ::: "memory");   // release (cumulative via bar.sync)
            st_flag(&g_flags[bid], target);
        }
        bool ok; int spins = 0;
        do {
            uint4 v = ld_flags4(&g_flags[threadIdx.x * 4]);
            ok = v.x >= target && v.y >= target && v.z >= target && v.w >= target;
            if (!ok && ++spins > 128) __nanosleep(64);
        } while (!__all_sync(0xffffffffu, ok));
        asm volatile("membar.gl;" ::: "memory");       // acquire
    }
    __syncthreads();
}

// ---------------- flag zero (also shifts ncu capture slot to a recurrence) ----
__global__ void flag_zero_kernel()
{
    if (threadIdx.x < NCTA) g_flags[threadIdx.x] = 0;
}

// ---------------- gx GEMM: C[4096,3072] = A @ W_ih^T + b (unchanged) ----------
__global__ void __launch_bounds__(256) gemm_gx_kernel(
    const float* __restrict__ A, const float* __restrict__ W,
    const float* __restrict__ bias)
{
    __shared__ float As[16][132];
    __shared__ float Bs[16][68];

    const int bm = blockIdx.y * 128;
    const int bn = blockIdx.x * 64;
    const int tid = threadIdx.x;

    ull acc[8][2];
#pragma unroll
    for (int i = 0; i < 8; i++) { acc[i][0] = 0ull; acc[i][1] = 0ull; }

    const int tx = tid & 15;
    const int ty = tid >> 4;

    for (int k0 = 0; k0 < IDIM; k0 += 16) {
#pragma unroll
        for (int j = 0; j < 2; j++) {
            int lid = tid + j * 256;
            int row = lid >> 2;
            int kk  = (lid & 3) * 4;
            float4 v = *(const float4*)&A[(size_t)(bm + row) * IDIM + k0 + kk];
            As[kk + 0][row] = v.x; As[kk + 1][row] = v.y;
            As[kk + 2][row] = v.z; As[kk + 3][row] = v.w;
        }
        {
            int row = tid >> 2;
            int kk  = (tid & 3) * 4;
            float4 v = *(const float4*)&W[(size_t)(bn + row) * IDIM + k0 + kk];
            Bs[kk + 0][row] = v.x; Bs[kk + 1][row] = v.y;
            Bs[kk + 2][row] = v.z; Bs[kk + 3][row] = v.w;
        }
        __syncthreads();

#pragma unroll
        for (int kk = 0; kk < 16; kk++) {
            float4 a0 = *(const float4*)&As[kk][ty * 8];
            float4 a1 = *(const float4*)&As[kk][ty * 8 + 4];
            ulonglong2 b2 = *(const ulonglong2*)&Bs[kk][tx * 4];
            float av[8] = {a0.x, a0.y, a0.z, a0.w, a1.x, a1.y, a1.z, a1.w};
#pragma unroll
            for (int i = 0; i < 8; i++) {
                ull ad = pack2(av[i], av[i]);
                fma2(acc[i][0], ad, b2.x);
                fma2(acc[i][1], ad, b2.y);
            }
        }
        __syncthreads();
    }

#pragma unroll
    for (int i = 0; i < 8; i++) {
        int m = bm + ty * 8 + i;
        float c0, c1, c2, c3;
        unpack2(acc[i][0], c0, c1);
        unpack2(acc[i][1], c2, c3);
        int n = bn + tx * 4;
        g_gx[(size_t)m * G3 + n + 0] = c0 + bias[n + 0];
        g_gx[(size_t)m * G3 + n + 1] = c1 + bias[n + 1];
        g_gx[(size_t)m * G3 + n + 2] = c2 + bias[n + 2];
        g_gx[(size_t)m * G3 + n + 3] = c3 + bias[n + 3];
    }
}

// ---------------- init h ----------------
__global__ void init_h_kernel(const float* __restrict__ h0)
{
    int i = blockIdx.x * blockDim.x + threadIdx.x;
    if (i < BATCH * HDIM) g_h[i] = h0[i];
}

// ---------------- persistent recurrence (3 barriers/step) ----------------
// smem (floats): WsA[256][68], WsB[128][68], HsA[256][68]; HsB overlays the
// half of HsA not used as the rh source (phase-B k-range ⊆ phase-A k-range).
#define SM_WA 0
#define SM_WB (256 * 68)
#define SM_HA (SM_WB + 128 * 68)
#define SMEM_FLOATS (SM_HA + 256 * 68)   // 43520 floats = 174,080 B

__global__ void __launch_bounds__(256, 1) recurrence_kernel(
    int c0, const float* __restrict__ Whh, const float* __restrict__ bhh,
    float* __restrict__ Y)
{
    extern __shared__ float sm[];
    float* WsA = sm + SM_WA;
    float* WsB = sm + SM_WB;
    float* HsA = sm + SM_HA;

    const int tid = threadIdx.x;
    const int bid = blockIdx.x;
    const int gtid = bid * 256 + tid;

    // phase A role: 32 n-groups x 4 k-splits
    const int ksA = bid & 3, ngA = bid >> 2;
    const int kA0 = ksA * 256, nA0 = ngA * 64;
    // phase B role: chosen so [kB0,kB0+128) ⊆ [kA0,kA0+256)
    const int e   = (bid >> 2) & 1;
    const int ksB = (bid & 3) * 2 + e;       // bijection over 0..7
    const int ngB = bid >> 3;
    const int kB0 = ksB * 128;               // == kA0 + 128*e
    const int nB0 = ngB * 64;

    float* HsB = HsA + (e ? 0 : 128 * 68);   // disjoint from rh source rows

    // resident weights (k-major, stride 68)
    for (int idx = tid; idx < 64 * 256; idx += 256) {
        int n = idx >> 8, k = idx & 255;
        WsA[k * 68 + n] = __ldg(&Whh[(size_t)(nA0 + n) * HDIM + kA0 + k]);
    }
    for (int idx = tid; idx < 64 * 128; idx += 256) {
        int n = idx >> 7, k = idx & 127;
        WsB[k * 68 + n] = __ldg(&Whh[(size_t)(2048 + nB0 + n) * HDIM + kB0 + k]);
    }

    const int tx = tid & 15, ty = tid >> 4;
    const int b0 = ty * 4;                   // batch base for GEMM tiles
    const int cA = tx * 4;                   // n-col base

    // rh-build mapping
    const int ncR = tid & 63;                // n within 64-group (warp-coalesced)
    const int bbR = tid >> 6;                // 0..3

    unsigned target;
    {
        unsigned t0;
        asm volatile("ld.global.cg.u32 %0, [%1];" : "=r"(t0)
                     : "l"(&g_flags[bid]) : "memory");
        target = t0;
    }

    __syncthreads();

    for (int tc = 0; tc < CHUNK; tc++) {
        const float* gx_t = g_gx + (size_t)tc * BATCH * G3;

        // ---- stage h slice [256 k x 64 b], k-major ----
        for (int it = tid; it < 64 * 64; it += 256) {
            int q = it >> 6;          // k-quad 0..63
            int b = it & 63;
            float4 v = __ldcg((const float4*)&g_h[b * HDIM + kA0 + q * 4]);
            HsA[(q * 4 + 0) * 68 + b] = v.x;
            HsA[(q * 4 + 1) * 68 + b] = v.y;
            HsA[(q * 4 + 2) * 68 + b] = v.z;
            HsA[(q * 4 + 3) * 68 + b] = v.w;
        }
        __syncthreads();

        // ---- phase A GEMM: partial[64b x 64n] over k in [kA0,kA0+256) ----
        {
            float acc[4][4];
#pragma unroll
            for (int i = 0; i < 4; i++)
#pragma unroll
                for (int j = 0; j < 4; j++) acc[i][j] = 0.f;

#pragma unroll 8
            for (int kk = 0; kk < 256; kk++) {
                float4 h4 = *(const float4*)&HsA[kk * 68 + b0];
                float4 w4 = *(const float4*)&WsA[kk * 68 + cA];
                acc[0][0] += h4.x * w4.x; acc[0][1] += h4.x * w4.y;
                acc[0][2] += h4.x * w4.z; acc[0][3] += h4.x * w4.w;
                acc[1][0] += h4.y * w4.x; acc[1][1] += h4.y * w4.y;
                acc[1][2] += h4.y * w4.z; acc[1][3] += h4.y * w4.w;
                acc[2][0] += h4.z * w4.x; acc[2][1] += h4.z * w4.y;
                acc[2][2] += h4.z * w4.z; acc[2][3] += h4.z * w4.w;
                acc[3][0] += h4.w * w4.x; acc[3][1] += h4.w * w4.y;
                acc[3][2] += h4.w * w4.z; acc[3][3] += h4.w * w4.w;
            }

            float* pA = g_partA + ((size_t)(ksA * 32 + ngA)) * 4096;
#pragma unroll
            for (int i = 0; i < 4; i++)
                *(float4*)&pA[(b0 + i) * 64 + cA] =
                    make_float4(acc[i][0], acc[i][1], acc[i][2], acc[i][3]);
        }
        bar_sync(bid, ++target);   // barrier 1: partA visible

        // ---- build rh slice [128 k x 64 b] in smem (replaces finalize A) ----
        {
#pragma unroll
            for (int g = 0; g < 2; g++) {
                int n = kB0 + g * 64 + ncR;       // r-gate col == k index (<1024)
                int ngGrp = n >> 6;
                float bv = __ldg(&bhh[n]);
                int rsrc = (n - kA0) * 68;        // rh source row in HsA
                int rdst = (n - kB0) * 68;        // dest row in HsB
#pragma unroll 4
                for (int j = 0; j < 16; j++) {
                    int b = bbR * 16 + j;
                    const float* pA = g_partA + (size_t)ngGrp * 4096 + b * 64 + ncR;
                    float ps = __ldcg(pA + (size_t)0 * 32 * 4096)
                             + __ldcg(pA + (size_t)1 * 32 * 4096)
                             + __ldcg(pA + (size_t)2 * 32 * 4096)
                             + __ldcg(pA + (size_t)3 * 32 * 4096);
                    float x = ps + __ldg(&gx_t[(size_t)b * G3 + n]) + bv;
                    float r = 1.f / (1.f + __expf(-x));
                    HsB[rdst + b] = r * HsA[rsrc + b];
                }
            }
        }
        __syncthreads();

        // ---- phase B GEMM: partial[64b x 64n] over k in [kB0,kB0+128) ----
        {
            float acc[4][4];
#pragma unroll
            for (int i = 0; i < 4; i++)
#pragma unroll
                for (int j = 0; j < 4; j++) acc[i][j] = 0.f;

#pragma unroll 8
            for (int kk = 0; kk < 128; kk++) {
                float4 h4 = *(const float4*)&HsB[kk * 68 + b0];
                float4 w4 = *(const float4*)&WsB[kk * 68 + cA];
                acc[0][0] += h4.x * w4.x; acc[0][1] += h4.x * w4.y;
                acc[0][2] += h4.x * w4.z; acc[0][3] += h4.x * w4.w;
                acc[1][0] += h4.y * w4.x; acc[1][1] += h4.y * w4.y;
                acc[1][2] += h4.y * w4.z; acc[1][3] += h4.y * w4.w;
                acc[2][0] += h4.z * w4.x; acc[2][1] += h4.z * w4.y;
                acc[2][2] += h4.z * w4.z; acc[2][3] += h4.z * w4.w;
                acc[3][0] += h4.w * w4.x; acc[3][1] += h4.w * w4.y;
                acc[3][2] += h4.w * w4.z; acc[3][3] += h4.w * w4.w;
            }

            float* pB = g_partB + ((size_t)(ksB * 16 + ngB)) * 4096;
#pragma unroll
            for (int i = 0; i < 4; i++)
                *(float4*)&pB[(b0 + i) * 64 + cA] =
                    make_float4(acc[i][0], acc[i][1], acc[i][2], acc[i][3]);
        }
        bar_sync(bid, ++target);   // barrier 2: partB visible

        // ---- finalize: z from partA, n from partB, blend, write h & Y ----
        {
            int e0 = gtid * 2;
            int b = e0 >> 10, n = e0 & 1023;
            int ng2 = n >> 6, nc2 = n & 63;

            const float* baseN = g_partB + (size_t)ng2 * 4096 + b * 64 + nc2;
            float nx = 0.f, ny = 0.f;
#pragma unroll
            for (int ks = 0; ks < 8; ks++) {
                float2 p = __ldcg((const float2*)(baseN + (size_t)ks * 16 * 4096));
                nx += p.x; ny += p.y;
            }
            const float* baseZ = g_partA + (size_t)(16 + ng2) * 4096 + b * 64 + nc2;
            float zx = 0.f, zy = 0.f;
#pragma unroll
            for (int ks = 0; ks < 4; ks++) {
                float2 p = __ldcg((const float2*)(baseZ + (size_t)ks * 32 * 4096));
                zx += p.x; zy += p.y;
            }

            float2 gZ = __ldg((const float2*)&gx_t[(size_t)b * G3 + 1024 + n]);
            float2 gN = __ldg((const float2*)&gx_t[(size_t)b * G3 + 2048 + n]);
            float2 bZ = __ldg((const float2*)&bhh[1024 + n]);
            float2 bN = __ldg((const float2*)&bhh[2048 + n]);

            float z0 = 1.f / (1.f + __expf(-(zx + gZ.x + bZ.x)));
            float z1 = 1.f / (1.f + __expf(-(zy + gZ.y + bZ.y)));
            float n0 = 2.f / (1.f + __expf(-2.f * (nx + gN.x + bN.x))) - 1.f;
            float n1 = 2.f / (1.f + __expf(-2.f * (ny + gN.y + bN.y))) - 1.f;

            float2 ho = __ldcg((const float2*)&g_h[b * HDIM + n]);
            float hn0 = (1.f - z0) * n0 + z0 * ho.x;
            float hn1 = (1.f - z1) * n1 + z1 * ho.y;
            *(float2*)&g_h[b * HDIM + n] = make_float2(hn0, hn1);
            int t = c0 + tc;
            *(float2*)&Y[((size_t)t * BATCH + b) * HDIM + n] = make_float2(hn0, hn1);
        }
        if (tc < CHUNK - 1) bar_sync(bid, ++target);   // barrier 3
    }
}

// ---------------- write Y_h ----------------
__global__ void write_yh_kernel(float* __restrict__ out_tail)
{
    int i = blockIdx.x * blockDim.x + threadIdx.x;
    if (i < BATCH * HDIM) out_tail[i] = g_h[i];
}

// ---------------- launch ----------------
extern "C" void kernel_launch(void* const* d_in, const int* in_sizes, int n_in,
                              void* d_out, int out_size)
{
    const float* input  = (const float*)d_in[0];
    const float* h0     = (const float*)d_in[1];
    const float* w_ih   = (const float*)d_in[2];
    const float* w_hh   = (const float*)d_in[3];
    const float* b_ih   = (const float*)d_in[4];
    const float* b_hh   = (const float*)d_in[5];
    float* out = (float*)d_out;

    const int smem_bytes = SMEM_FLOATS * sizeof(float);   // 174,080 B
    cudaFuncSetAttribute(recurrence_kernel,
                         cudaFuncAttributeMaxDynamicSharedMemorySize, smem_bytes);

    init_h_kernel<<<(BATCH * HDIM + 255) / 256, 256>>>(h0);   // launch 1
    flag_zero_kernel<<<1, 128>>>();                            // launch 2 (parity)

    dim3 ggrid(G3 / 64, (CHUNK * BATCH) / 128);
    for (int c = 0; c < NCHUNK; c++) {
        gemm_gx_kernel<<<ggrid, 256>>>(input + (size_t)c * CHUNK * BATCH * IDIM, w_ih, b_ih);
        recurrence_kernel<<<NCTA, 256, smem_bytes>>>(c * CHUNK, w_hh, b_hh, out);
    }

    write_yh_kernel<<<(BATCH * HDIM + 255) / 256, 256>>>(out + (size_t)SEQ * BATCH * HDIM);
}

// round 14
// speedup vs baseline: 1.0707x; 1.0667x over previous
// v7 — R10-proven barrier (backoff restored) + finalize-input prefetches
#include <cuda_runtime.h>
#include <cstdint>

#define SEQ 512
#define BATCH 64
#define IDIM 1024
#define HDIM 1024
#define G3 3072
#define CHUNK 64
#define NCHUNK (SEQ / CHUNK)
#define NCTA 128

typedef unsigned long long ull;

// ---------------- scratch ----------------
__device__ float g_gx[(size_t)CHUNK * BATCH * G3];   // 50 MB
__device__ float g_h[BATCH * HDIM];
__device__ float g_z[BATCH * HDIM];
__device__ float g_rh[BATCH * HDIM];
__device__ float g_partA[4 * 32 * 64 * 64];          // [ksA*32+ngA][b][nc]
__device__ float g_partB[8 * 16 * 64 * 64];          // [ksB*16+ngB][b][nc]
__device__ unsigned g_flags[NCTA];

// ---------------- f32x2 helpers (gemm only) ----------------
__device__ __forceinline__ ull pack2(float x, float y) {
    ull r; asm("mov.b64 %0, {%1, %2};" : "=l"(r) : "f"(x), "f"(y)); return r;
}
__device__ __forceinline__ void unpack2(ull v, float& x, float& y) {
    asm("mov.b64 {%0, %1}, %2;" : "=f"(x), "=f"(y) : "l"(v));
}
__device__ __forceinline__ void fma2(ull& d, ull a, ull b) {
    asm("fma.rn.f32x2 %0, %1, %2, %0;" : "+l"(d) : "l"(a), "l"(b));
}

// ---------------- pinned-issue loads ----------------
__device__ __forceinline__ uint4 ld_flags4(const unsigned* p) {
    uint4 v;
    asm volatile("ld.global.cg.v4.u32 {%0,%1,%2,%3}, [%4];"
                 : "=r"(v.x), "=r"(v.y), "=r"(v.z), "=r"(v.w)
                 : "l"(p) : "memory");
    return v;
}
__device__ __forceinline__ void st_flag(unsigned* p, unsigned v) {
    asm volatile("st.global.cg.u32 [%0], %1;" :: "l"(p), "r"(v) : "memory");
}
__device__ __forceinline__ float4 ldg4_pin(const float* p) {
    float4 v;
    asm volatile("ld.global.nc.v4.f32 {%0,%1,%2,%3}, [%4];"
                 : "=f"(v.x), "=f"(v.y), "=f"(v.z), "=f"(v.w) : "l"(p));
    return v;
}
__device__ __forceinline__ float4 ldcg4_pin(const float* p) {
    float4 v;
    asm volatile("ld.global.cg.v4.f32 {%0,%1,%2,%3}, [%4];"
                 : "=f"(v.x), "=f"(v.y), "=f"(v.z), "=f"(v.w) : "l"(p));
    return v;
}
__device__ __forceinline__ float2 ldg2_pin(const float* p) {
    float2 v;
    asm volatile("ld.global.nc.v2.f32 {%0,%1}, [%2];"
                 : "=f"(v.x), "=f"(v.y) : "l"(p));
    return v;
}
__device__ __forceinline__ float2 ldcg2_pin(const float* p) {
    float2 v;
    asm volatile("ld.global.cg.v2.f32 {%0,%1}, [%2];"
                 : "=f"(v.x), "=f"(v.y) : "l"(p));
    return v;
}

// ---------------- flag-array grid barrier (backoff restored — load-bearing) ----
__device__ __forceinline__ void bar_sync(int bid, unsigned target)
{
    __syncthreads();
    if (threadIdx.x < 32) {
        if (threadIdx.x == 0) {
            asm volatile("membar.gl;" ::: "memory");   // release (cumulative)
            st_flag(&g_flags[bid], target);
        }
        bool ok; int spins = 0;
        do {
            uint4 v = ld_flags4(&g_flags[threadIdx.x * 4]);
            ok = v.x >= target && v.y >= target && v.z >= target && v.w >= target;
            if (!ok && ++spins > 128) __nanosleep(64);
        } while (!__all_sync(0xffffffffu, ok));
        asm volatile("membar.gl;" ::: "memory");       // acquire
    }
    __syncthreads();
}

// ---------------- flag zero / launch parity ----------------
__global__ void flag_zero_kernel()
{
    if (threadIdx.x < NCTA) g_flags[threadIdx.x] = 0;
}

// ---------------- gx GEMM (unchanged) ----------------
__global__ void __launch_bounds__(256) gemm_gx_kernel(
    const float* __restrict__ A, const float* __restrict__ W,
    const float* __restrict__ bias)
{
    __shared__ float As[16][132];
    __shared__ float Bs[16][68];

    const int bm = blockIdx.y * 128;
    const int bn = blockIdx.x * 64;
    const int tid = threadIdx.x;

    ull acc[8][2];
#pragma unroll
    for (int i = 0; i < 8; i++) { acc[i][0] = 0ull; acc[i][1] = 0ull; }

    const int tx = tid & 15;
    const int ty = tid >> 4;

    for (int k0 = 0; k0 < IDIM; k0 += 16) {
#pragma unroll
        for (int j = 0; j < 2; j++) {
            int lid = tid + j * 256;
            int row = lid >> 2;
            int kk  = (lid & 3) * 4;
            float4 v = *(const float4*)&A[(size_t)(bm + row) * IDIM + k0 + kk];
            As[kk + 0][row] = v.x; As[kk + 1][row] = v.y;
            As[kk + 2][row] = v.z; As[kk + 3][row] = v.w;
        }
        {
            int row = tid >> 2;
            int kk  = (tid & 3) * 4;
            float4 v = *(const float4*)&W[(size_t)(bn + row) * IDIM + k0 + kk];
            Bs[kk + 0][row] = v.x; Bs[kk + 1][row] = v.y;
            Bs[kk + 2][row] = v.z; Bs[kk + 3][row] = v.w;
        }
        __syncthreads();

#pragma unroll
        for (int kk = 0; kk < 16; kk++) {
            float4 a0 = *(const float4*)&As[kk][ty * 8];
            float4 a1 = *(const float4*)&As[kk][ty * 8 + 4];
            ulonglong2 b2 = *(const ulonglong2*)&Bs[kk][tx * 4];
            float av[8] = {a0.x, a0.y, a0.z, a0.w, a1.x, a1.y, a1.z, a1.w};
#pragma unroll
            for (int i = 0; i < 8; i++) {
                ull ad = pack2(av[i], av[i]);
                fma2(acc[i][0], ad, b2.x);
                fma2(acc[i][1], ad, b2.y);
            }
        }
        __syncthreads();
    }

#pragma unroll
    for (int i = 0; i < 8; i++) {
        int m = bm + ty * 8 + i;
        float c0, c1, c2, c3;
        unpack2(acc[i][0], c0, c1);
        unpack2(acc[i][1], c2, c3);
        int n = bn + tx * 4;
        g_gx[(size_t)m * G3 + n + 0] = c0 + bias[n + 0];
        g_gx[(size_t)m * G3 + n + 1] = c1 + bias[n + 1];
        g_gx[(size_t)m * G3 + n + 2] = c2 + bias[n + 2];
        g_gx[(size_t)m * G3 + n + 3] = c3 + bias[n + 3];
    }
}

// ---------------- init h ----------------
__global__ void init_h_kernel(const float* __restrict__ h0)
{
    int i = blockIdx.x * blockDim.x + threadIdx.x;
    if (i < BATCH * HDIM) g_h[i] = h0[i];
}

// ---------------- persistent recurrence ----------------
// smem (floats): WsA[256][68], WsB[128][68], Hs[256][68] (k-major)
#define SM_WA 0
#define SM_WB (256 * 68)
#define SM_HS (SM_WB + 128 * 68)
#define SMEM_FLOATS (SM_HS + 256 * 68)   // 174,080 B

__global__ void __launch_bounds__(256, 1) recurrence_kernel(
    int c0, const float* __restrict__ Whh, const float* __restrict__ bhh,
    float* __restrict__ Y)
{
    extern __shared__ float sm[];
    float* WsA = sm + SM_WA;
    float* WsB = sm + SM_WB;
    float* Hs  = sm + SM_HS;

    const int tid = threadIdx.x;
    const int bid = blockIdx.x;
    const int gtid = bid * 256 + tid;

    const int ngA = bid >> 2, ksA = bid & 3;
    const int nA0 = ngA * 64, kA0 = ksA * 256;
    const int ngB = bid >> 3, ksB = bid & 7;
    const int nB0 = ngB * 64, kB0 = ksB * 128;

    // resident weights (k-major, stride 68)
    for (int idx = tid; idx < 64 * 256; idx += 256) {
        int n = idx >> 8, k = idx & 255;
        WsA[k * 68 + n] = __ldg(&Whh[(size_t)(nA0 + n) * HDIM + kA0 + k]);
    }
    for (int idx = tid; idx < 64 * 128; idx += 256) {
        int n = idx >> 7, k = idx & 127;
        WsB[k * 68 + n] = __ldg(&Whh[(size_t)(2048 + nB0 + n) * HDIM + kB0 + k]);
    }

    const int tx = tid & 15, ty = tid >> 4;
    const int b0 = ty * 4;
    const int cA = tx * 4;

    // finalize-A coords + loop-invariant bias
    const int eA = gtid * 4;
    const int bA = eA >> 11, nA = eA & 2047;
    const float4 bbA = *(const float4*)&bhh[nA];
    const bool isR = (nA < HDIM);

    // finalize-B coords + loop-invariant bias
    const int eB = gtid * 2;
    const int bB = eB >> 10, nB = eB & 1023;
    const float2 bN = *(const float2*)&bhh[2048 + nB];

    unsigned target;
    {
        unsigned t0;
        asm volatile("ld.global.cg.u32 %0, [%1];" : "=r"(t0)
                     : "l"(&g_flags[bid]) : "memory");
        target = t0;
    }

    __syncthreads();

    for (int tc = 0; tc < CHUNK; tc++) {
        const float* gx_t = g_gx + (size_t)tc * BATCH * G3;

        // ---- stage h slice [256 k x 64 b], k-major ----
        for (int it = tid; it < 64 * 64; it += 256) {
            int q = it >> 6;
            int b = it & 63;
            float4 v = ldcg4_pin(&g_h[b * HDIM + kA0 + q * 4]);
            Hs[(q * 4 + 0) * 68 + b] = v.x;
            Hs[(q * 4 + 1) * 68 + b] = v.y;
            Hs[(q * 4 + 2) * 68 + b] = v.z;
            Hs[(q * 4 + 3) * 68 + b] = v.w;
        }
        __syncthreads();

        // ---- PREFETCH finalize-A inputs (overlap with phase-A GEMM) ----
        float4 gA = ldg4_pin(&gx_t[(size_t)bA * G3 + nA]);
        float4 hA = make_float4(0.f, 0.f, 0.f, 0.f);
        if (isR) hA = ldcg4_pin(&g_h[bA * HDIM + nA]);

        // ---- phase A GEMM: partial[64b x 64n], k in [kA0,kA0+256) ----
        {
            float acc[4][4];
#pragma unroll
            for (int i = 0; i < 4; i++)
#pragma unroll
                for (int j = 0; j < 4; j++) acc[i][j] = 0.f;

#pragma unroll 8
            for (int kk = 0; kk < 256; kk++) {
                float4 h4 = *(const float4*)&Hs[kk * 68 + b0];
                float4 w4 = *(const float4*)&WsA[kk * 68 + cA];
                acc[0][0] += h4.x * w4.x; acc[0][1] += h4.x * w4.y;
                acc[0][2] += h4.x * w4.z; acc[0][3] += h4.x * w4.w;
                acc[1][0] += h4.y * w4.x; acc[1][1] += h4.y * w4.y;
                acc[1][2] += h4.y * w4.z; acc[1][3] += h4.y * w4.w;
                acc[2][0] += h4.z * w4.x; acc[2][1] += h4.z * w4.y;
                acc[2][2] += h4.z * w4.z; acc[2][3] += h4.z * w4.w;
                acc[3][0] += h4.w * w4.x; acc[3][1] += h4.w * w4.y;
                acc[3][2] += h4.w * w4.z; acc[3][3] += h4.w * w4.w;
            }

            float* pA = g_partA + ((size_t)(ksA * 32 + ngA)) * 4096;
#pragma unroll
            for (int i = 0; i < 4; i++)
                *(float4*)&pA[(b0 + i) * 64 + cA] =
                    make_float4(acc[i][0], acc[i][1], acc[i][2], acc[i][3]);
        }
        bar_sync(bid, ++target);   // barrier 1: partA visible

        // ---- finalize A: only partial sums post-barrier ----
        {
            int png = nA >> 6, pnc = nA & 63;
            const float* base = g_partA + (size_t)png * 4096 + bA * 64 + pnc;
            float4 s  = ldcg4_pin(base + (size_t)0 * 32 * 4096);
            float4 p1 = ldcg4_pin(base + (size_t)1 * 32 * 4096);
            float4 p2 = ldcg4_pin(base + (size_t)2 * 32 * 4096);
            float4 p3 = ldcg4_pin(base + (size_t)3 * 32 * 4096);
            s.x += p1.x + p2.x + p3.x; s.y += p1.y + p2.y + p3.y;
            s.z += p1.z + p2.z + p3.z; s.w += p1.w + p2.w + p3.w;
            float s0 = 1.f / (1.f + __expf(-(s.x + gA.x + bbA.x)));
            float s1 = 1.f / (1.f + __expf(-(s.y + gA.y + bbA.y)));
            float s2 = 1.f / (1.f + __expf(-(s.z + gA.z + bbA.z)));
            float s3 = 1.f / (1.f + __expf(-(s.w + gA.w + bbA.w)));
            if (isR) {
                *(float4*)&g_rh[bA * HDIM + nA] =
                    make_float4(s0 * hA.x, s1 * hA.y, s2 * hA.z, s3 * hA.w);
            } else {
                *(float4*)&g_z[bA * HDIM + (nA - HDIM)] = make_float4(s0, s1, s2, s3);
            }
        }
        bar_sync(bid, ++target);   // barrier 2: rh/z visible

        // ---- PREFETCH finalize-B inputs (overlap with phase-B GEMM) ----
        float2 gN = ldg2_pin(&gx_t[(size_t)bB * G3 + 2048 + nB]);
        float2 z2 = ldcg2_pin(&g_z[bB * HDIM + nB]);
        float2 ho = ldcg2_pin(&g_h[bB * HDIM + nB]);

        // ---- stage rh slice [128 k x 64 b], k-major ----
        for (int it = tid; it < 32 * 64; it += 256) {
            int q = it >> 6;
            int b = it & 63;
            float4 v = ldcg4_pin(&g_rh[b * HDIM + kB0 + q * 4]);
            Hs[(q * 4 + 0) * 68 + b] = v.x;
            Hs[(q * 4 + 1) * 68 + b] = v.y;
            Hs[(q * 4 + 2) * 68 + b] = v.z;
            Hs[(q * 4 + 3) * 68 + b] = v.w;
        }
        __syncthreads();

        // ---- phase B GEMM: partial[64b x 64n], k in [kB0,kB0+128) ----
        {
            float acc[4][4];
#pragma unroll
            for (int i = 0; i < 4; i++)
#pragma unroll
                for (int j = 0; j < 4; j++) acc[i][j] = 0.f;

#pragma unroll 8
            for (int kk = 0; kk < 128; kk++) {
                float4 h4 = *(const float4*)&Hs[kk * 68 + b0];
                float4 w4 = *(const float4*)&WsB[kk * 68 + cA];
                acc[0][0] += h4.x * w4.x; acc[0][1] += h4.x * w4.y;
                acc[0][2] += h4.x * w4.z; acc[0][3] += h4.x * w4.w;
                acc[1][0] += h4.y * w4.x; acc[1][1] += h4.y * w4.y;
                acc[1][2] += h4.y * w4.z; acc[1][3] += h4.y * w4.w;
                acc[2][0] += h4.z * w4.x; acc[2][1] += h4.z * w4.y;
                acc[2][2] += h4.z * w4.z; acc[2][3] += h4.z * w4.w;
                acc[3][0] += h4.w * w4.x; acc[3][1] += h4.w * w4.y;
                acc[3][2] += h4.w * w4.z; acc[3][3] += h4.w * w4.w;
            }

            float* pB = g_partB + ((size_t)(ksB * 16 + ngB)) * 4096;
#pragma unroll
            for (int i = 0; i < 4; i++)
                *(float4*)&pB[(b0 + i) * 64 + cA] =
                    make_float4(acc[i][0], acc[i][1], acc[i][2], acc[i][3]);
        }
        bar_sync(bid, ++target);   // barrier 3: partB visible

        // ---- finalize B: partial sums + blend (rest prefetched) ----
        {
            int png = nB >> 6, pnc = nB & 63;
            const float* base = g_partB + (size_t)png * 4096 + bB * 64 + pnc;
            float sx = 0.f, sy = 0.f;
#pragma unroll
            for (int ks = 0; ks < 8; ks++) {
                float2 p = ldcg2_pin(base + (size_t)ks * 16 * 4096);
                sx += p.x; sy += p.y;
            }
            float x0 = sx + gN.x + bN.x;
            float x1 = sy + gN.y + bN.y;
            float n0 = 2.f / (1.f + __expf(-2.f * x0)) - 1.f;
            float n1 = 2.f / (1.f + __expf(-2.f * x1)) - 1.f;
            float hn0 = (1.f - z2.x) * n0 + z2.x * ho.x;
            float hn1 = (1.f - z2.y) * n1 + z2.y * ho.y;
            *(float2*)&g_h[bB * HDIM + nB] = make_float2(hn0, hn1);
            int t = c0 + tc;
            *(float2*)&Y[((size_t)t * BATCH + bB) * HDIM + nB] = make_float2(hn0, hn1);
        }
        if (tc < CHUNK - 1) bar_sync(bid, ++target);   // barrier 4
    }
}

// ---------------- write Y_h ----------------
__global__ void write_yh_kernel(float* __restrict__ out_tail)
{
    int i = blockIdx.x * blockDim.x + threadIdx.x;
    if (i < BATCH * HDIM) out_tail[i] = g_h[i];
}

// ---------------- launch ----------------
extern "C" void kernel_launch(void* const* d_in, const int* in_sizes, int n_in,
                              void* d_out, int out_size)
{
    const float* input  = (const float*)d_in[0];
    const float* h0     = (const float*)d_in[1];
    const float* w_ih   = (const float*)d_in[2];
    const float* w_hh   = (const float*)d_in[3];
    const float* b_ih   = (const float*)d_in[4];
    const float* b_hh   = (const float*)d_in[5];
    float* out = (float*)d_out;

    const int smem_bytes = SMEM_FLOATS * sizeof(float);
    cudaFuncSetAttribute(recurrence_kernel,
                         cudaFuncAttributeMaxDynamicSharedMemorySize, smem_bytes);

    init_h_kernel<<<(BATCH * HDIM + 255) / 256, 256>>>(h0);
    flag_zero_kernel<<<1, 128>>>();

    dim3 ggrid(G3 / 64, (CHUNK * BATCH) / 128);
    for (int c = 0; c < NCHUNK; c++) {
        gemm_gx_kernel<<<ggrid, 256>>>(input + (size_t)c * CHUNK * BATCH * IDIM, w_ih, b_ih);
        recurrence_kernel<<<NCTA, 256, smem_bytes>>>(c * CHUNK, w_hh, b_hh, out);
    }

    write_yh_kernel<<<(BATCH * HDIM + 255) / 256, 256>>>(out + (size_t)SEQ * BATCH * HDIM);
}